// round 4
// baseline (speedup 1.0000x reference)
#include <cuda_runtime.h>
#include <cstdint>
#include <cstddef>

#define NN 32768
#define EE 524288
#define HH 128
#define GG 64
#define NG 512   // nodes per graph

// ---------------- device scratch (static, no allocations; float4 => 16B aligned) ----------------
__device__ int    g_ei64;                      // 1 if edge_index is int64, 0 if int32
__device__ int    g_cnt[NN];                   // in-degree histogram (excl self-loop)
__device__ int    g_off[NN + 1];               // CSR offsets
__device__ int    g_cur[NN];                   // fill cursors
__device__ int    g_srcs[EE];                  // CSR source ids (grouped by dst)
__device__ float  g_dinv[NN];
__device__ float4 g_hs[NN * 32];               // messages; later reused for V
__device__ float4 g_h [NN * 32];               // post-conv features
__device__ float4 g_q [NN * 32];
__device__ float4 g_k [NN * 32];
__device__ float  g_rowm[GG * NG];
__device__ float  g_rowz[GG * NG];             // 1/Z per row
__device__ float  g_w[GG * NG];                // column weights

// ---------------- edge index accessors (dtype-flexible, trap-safe) ----------------
__device__ __forceinline__ int edge_src(const void* ei, int e) {
    int v = g_ei64 ? (int)((const long long*)ei)[e] : ((const int*)ei)[e];
    return v & (NN - 1);
}
__device__ __forceinline__ int edge_dst(const void* ei, int e) {
    int v = g_ei64 ? (int)((const long long*)ei)[EE + e] : ((const int*)ei)[EE + e];
    return v & (NN - 1);
}

// detect dtype: first 1024 int64-slots all in [0,NN) => int64 data (reads 8KB, safe either way)
__global__ void k_dtype(const void* ei) {
    __shared__ int s_ok;
    if (threadIdx.x == 0) s_ok = 1;
    __syncthreads();
    const long long* p = (const long long*)ei;
    int bad = 0;
#pragma unroll
    for (int i = 0; i < 4; i++) {
        long long v = p[threadIdx.x * 4 + i];
        if (v < 0 || v >= NN) bad = 1;
    }
    if (bad) atomicExch(&s_ok, 0);
    __syncthreads();
    if (threadIdx.x == 0) g_ei64 = s_ok;
}

// ---------------- CSR build ----------------
__global__ void k_zero_cnt() {
    int i = blockIdx.x * blockDim.x + threadIdx.x;
    if (i < NN) g_cnt[i] = 0;
}

__global__ void k_hist(const void* __restrict__ ei) {
    int e = blockIdx.x * blockDim.x + threadIdx.x;
    if (e < EE) atomicAdd(&g_cnt[edge_dst(ei, e)], 1);
}

// one block, 1024 threads: exclusive scan of g_cnt into g_off/g_cur, plus dinv
__global__ void __launch_bounds__(1024) k_scan() {
    __shared__ int sh[1024];
    int t = threadIdx.x;
    int base = t * 32;
    int local[32];
    int s = 0;
#pragma unroll
    for (int k = 0; k < 32; k++) { local[k] = g_cnt[base + k]; s += local[k]; }
    sh[t] = s;
    __syncthreads();
#pragma unroll
    for (int o = 1; o < 1024; o <<= 1) {
        int v = (t >= o) ? sh[t - o] : 0;
        __syncthreads();
        sh[t] += v;
        __syncthreads();
    }
    int run = (t > 0) ? sh[t - 1] : 0;
#pragma unroll
    for (int k = 0; k < 32; k++) {
        g_off[base + k] = run;
        g_cur[base + k] = run;
        g_dinv[base + k] = rsqrtf((float)local[k] + 1.0f);  // +1 self loop
        run += local[k];
    }
    if (t == 1023) g_off[NN] = run;
}

__global__ void k_fill(const void* __restrict__ ei) {
    int e = blockIdx.x * blockDim.x + threadIdx.x;
    if (e >= EE) return;
    int s = edge_src(ei, e);
    int d = edge_dst(ei, e);
    int slot = atomicAdd(&g_cur[d], 1);
    g_srcs[slot] = s;
}

// ---------------- GEMM: C[M,128] = A[M,128] @ W[128,128] ----------------
// 128x128 output tile per block, 256 threads, 8x8 microtile. K chunked by 32 (static smem).
// srcMode: 0 = Aext (harness input), 1 = g_h
// dstMode: 0 = g_hs (also V), 1 = g_q, 2 = g_k
// useRow != 0: multiply rows by g_dinv (conv message scaling)
__global__ void __launch_bounds__(256) k_gemm(const float* __restrict__ Aext,
                                              const float* __restrict__ W,
                                              const float* __restrict__ bias,
                                              int srcMode, int dstMode, int useRow) {
    __shared__ float As[128 * 33];
    __shared__ float Ws[32 * 128];
    const float* A = (srcMode == 0) ? Aext : (const float*)g_h;
    float4* C = (dstMode == 0) ? g_hs : (dstMode == 1) ? g_q : g_k;

    int tid = threadIdx.x;
    size_t m0 = (size_t)blockIdx.x * 128;
    const float4* A4 = (const float4*)(A + m0 * 128);
    const float4* W4 = (const float4*)W;

    int ty = tid >> 4, tx = tid & 15;
    float acc[8][8];
#pragma unroll
    for (int r = 0; r < 8; r++)
#pragma unroll
        for (int c = 0; c < 8; c++) acc[r][c] = 0.0f;

    for (int kc = 0; kc < 4; kc++) {
#pragma unroll
        for (int it = 0; it < 4; it++) {
            int idx = it * 256 + tid;
            int row = idx >> 3, k4 = idx & 7;
            float4 v = A4[row * 32 + kc * 8 + k4];
            float* p = &As[row * 33 + k4 * 4];
            p[0] = v.x; p[1] = v.y; p[2] = v.z; p[3] = v.w;
        }
#pragma unroll
        for (int it = 0; it < 4; it++) {
            int idx = it * 256 + tid;
            int kr = idx >> 5, c4 = idx & 31;
            ((float4*)Ws)[kr * 32 + c4] = W4[(kc * 32 + kr) * 32 + c4];
        }
        __syncthreads();

#pragma unroll 4
        for (int k = 0; k < 32; k++) {
            float a[8];
#pragma unroll
            for (int r = 0; r < 8; r++) a[r] = As[(ty * 8 + r) * 33 + k];
            float4 w0 = ((const float4*)Ws)[k * 32 + tx];
            float4 w1 = ((const float4*)Ws)[k * 32 + 16 + tx];
#pragma unroll
            for (int r = 0; r < 8; r++) {
                acc[r][0] += a[r] * w0.x; acc[r][1] += a[r] * w0.y;
                acc[r][2] += a[r] * w0.z; acc[r][3] += a[r] * w0.w;
                acc[r][4] += a[r] * w1.x; acc[r][5] += a[r] * w1.y;
                acc[r][6] += a[r] * w1.z; acc[r][7] += a[r] * w1.w;
            }
        }
        __syncthreads();
    }

    float4 b0 = make_float4(0.f, 0.f, 0.f, 0.f), b1v = b0;
    if (bias) { b0 = ((const float4*)bias)[tx]; b1v = ((const float4*)bias)[16 + tx]; }
#pragma unroll
    for (int r = 0; r < 8; r++) {
        size_t m = m0 + ty * 8 + r;
        float sc = useRow ? g_dinv[m] : 1.0f;
        float4 o0, o1;
        o0.x = acc[r][0] * sc + b0.x;  o0.y = acc[r][1] * sc + b0.y;
        o0.z = acc[r][2] * sc + b0.z;  o0.w = acc[r][3] * sc + b0.w;
        o1.x = acc[r][4] * sc + b1v.x; o1.y = acc[r][5] * sc + b1v.y;
        o1.z = acc[r][6] * sc + b1v.z; o1.w = acc[r][7] * sc + b1v.w;
        C[m * 32 + tx] = o0;
        C[m * 32 + 16 + tx] = o1;
    }
}

// ---------------- aggregate: h[i] = relu(dinv[i] * (hs[i] + sum_{s->i} hs[s]) + b) ----------------
__global__ void __launch_bounds__(256) k_aggregate(const float* __restrict__ b) {
    int t = blockIdx.x * blockDim.x + threadIdx.x;
    int i = t >> 5;
    if (i >= NN) return;
    int lane = t & 31;

    float4 acc = g_hs[(size_t)i * 32 + lane];   // self loop (hs already has dinv[src])
    int j = g_off[i];
    int end = g_off[i + 1];
    for (; j + 1 < end; j += 2) {
        int s0 = g_srcs[j], s1 = g_srcs[j + 1];
        float4 v0 = g_hs[(size_t)s0 * 32 + lane];
        float4 v1 = g_hs[(size_t)s1 * 32 + lane];
        acc.x += v0.x + v1.x; acc.y += v0.y + v1.y;
        acc.z += v0.z + v1.z; acc.w += v0.w + v1.w;
    }
    if (j < end) {
        int s0 = g_srcs[j];
        float4 v0 = g_hs[(size_t)s0 * 32 + lane];
        acc.x += v0.x; acc.y += v0.y; acc.z += v0.z; acc.w += v0.w;
    }
    float sc = g_dinv[i];
    float4 bb = ((const float4*)b)[lane];
    float4 o;
    o.x = fmaxf(acc.x * sc + bb.x, 0.f);
    o.y = fmaxf(acc.y * sc + bb.y, 0.f);
    o.z = fmaxf(acc.z * sc + bb.z, 0.f);
    o.w = fmaxf(acc.w * sc + bb.w, 0.f);
    g_h[(size_t)i * 32 + lane] = o;
}

#define SCALE 0.08838834764831845f  // 1/sqrt(128)

// ---------------- pass 1: per-row online softmax stats over recomputed scores ----------------
// block = (g, i-tile of 128 rows); sweeps all 4 j-tiles; online (max, sumexp) in registers.
__global__ void __launch_bounds__(256) k_rowstats2() {
    __shared__ float Qs[128 * 33];
    __shared__ float Kt[32 * 132];
    int g = blockIdx.y, ti = blockIdx.x;
    int tid = threadIdx.x;
    int ty = tid >> 4, tx = tid & 15;

    const float4* Qb = g_q + ((size_t)(g * NG + ti * 128)) * 32;

    float m[8], z[8];
#pragma unroll
    for (int r = 0; r < 8; r++) { m[r] = -1e30f; z[r] = 0.f; }

    for (int jt = 0; jt < 4; jt++) {
        const float4* Kb = g_k + ((size_t)(g * NG + jt * 128)) * 32;
        float acc[8][8];
#pragma unroll
        for (int r = 0; r < 8; r++)
#pragma unroll
            for (int c = 0; c < 8; c++) acc[r][c] = 0.0f;

        for (int kc = 0; kc < 4; kc++) {
#pragma unroll
            for (int it = 0; it < 4; it++) {
                int idx = it * 256 + tid;
                int row = idx >> 3, d4 = idx & 7;
                float4 qv = Qb[row * 32 + kc * 8 + d4];
                float* p = &Qs[row * 33 + d4 * 4];
                p[0] = qv.x; p[1] = qv.y; p[2] = qv.z; p[3] = qv.w;
                float4 kv = Kb[row * 32 + kc * 8 + d4];
                Kt[(d4 * 4 + 0) * 132 + row] = kv.x;
                Kt[(d4 * 4 + 1) * 132 + row] = kv.y;
                Kt[(d4 * 4 + 2) * 132 + row] = kv.z;
                Kt[(d4 * 4 + 3) * 132 + row] = kv.w;
            }
            __syncthreads();
#pragma unroll 4
            for (int d = 0; d < 32; d++) {
                float a[8];
#pragma unroll
                for (int r = 0; r < 8; r++) a[r] = Qs[(ty * 8 + r) * 33 + d];
                float4 w0 = *(const float4*)&Kt[d * 132 + tx * 4];
                float4 w1 = *(const float4*)&Kt[d * 132 + 64 + tx * 4];
#pragma unroll
                for (int r = 0; r < 8; r++) {
                    acc[r][0] += a[r] * w0.x; acc[r][1] += a[r] * w0.y;
                    acc[r][2] += a[r] * w0.z; acc[r][3] += a[r] * w0.w;
                    acc[r][4] += a[r] * w1.x; acc[r][5] += a[r] * w1.y;
                    acc[r][6] += a[r] * w1.z; acc[r][7] += a[r] * w1.w;
                }
            }
            __syncthreads();
        }

        // online update (scaled scores)
#pragma unroll
        for (int r = 0; r < 8; r++) {
            float lm = -1e30f;
#pragma unroll
            for (int c = 0; c < 8; c++) lm = fmaxf(lm, acc[r][c] * SCALE);
            float nm = fmaxf(m[r], lm);
            float za = 0.f;
#pragma unroll
            for (int c = 0; c < 8; c++) za += __expf(acc[r][c] * SCALE - nm);
            z[r] = z[r] * __expf(m[r] - nm) + za;
            m[r] = nm;
        }
    }

    // combine across the 16 tx-lanes sharing the same rows (same ty -> same warp half)
#pragma unroll
    for (int o = 1; o < 16; o <<= 1) {
#pragma unroll
        for (int r = 0; r < 8; r++) {
            float om = __shfl_xor_sync(0xffffffffu, m[r], o);
            float oz = __shfl_xor_sync(0xffffffffu, z[r], o);
            float nm = fmaxf(m[r], om);
            z[r] = z[r] * __expf(m[r] - nm) + oz * __expf(om - nm);
            m[r] = nm;
        }
    }
    if (tx == 0) {
#pragma unroll
        for (int r = 0; r < 8; r++) {
            int row = g * NG + ti * 128 + ty * 8 + r;
            g_rowm[row] = m[r];
            g_rowz[row] = 1.0f / z[r];
        }
    }
}

// ---------------- pass 2: column weights w_j = sum_i exp(s_ij - m_i) / Z_i ----------------
// block = (g, j-tile of 128 cols); sweeps all 4 i-tiles, recomputing scores.
__global__ void __launch_bounds__(256) k_colw() {
    __shared__ float Qs[128 * 33];
    __shared__ float Kt[32 * 132];
    __shared__ float sm_m[128];
    __shared__ float sm_zi[128];
    __shared__ float colw[128];
    int g = blockIdx.y, tj = blockIdx.x;
    int tid = threadIdx.x;
    int ty = tid >> 4, tx = tid & 15;

    if (tid < 128) colw[tid] = 0.f;
    const float4* Kb = g_k + ((size_t)(g * NG + tj * 128)) * 32;

    float wacc[8];
#pragma unroll
    for (int c = 0; c < 8; c++) wacc[c] = 0.f;

    for (int it4 = 0; it4 < 4; it4++) {
        if (tid < 128) {
            sm_m[tid]  = g_rowm[g * NG + it4 * 128 + tid];
            sm_zi[tid] = g_rowz[g * NG + it4 * 128 + tid];
        }
        const float4* Qb = g_q + ((size_t)(g * NG + it4 * 128)) * 32;
        float acc[8][8];
#pragma unroll
        for (int r = 0; r < 8; r++)
#pragma unroll
            for (int c = 0; c < 8; c++) acc[r][c] = 0.0f;

        for (int kc = 0; kc < 4; kc++) {
#pragma unroll
            for (int it = 0; it < 4; it++) {
                int idx = it * 256 + tid;
                int row = idx >> 3, d4 = idx & 7;
                float4 qv = Qb[row * 32 + kc * 8 + d4];
                float* p = &Qs[row * 33 + d4 * 4];
                p[0] = qv.x; p[1] = qv.y; p[2] = qv.z; p[3] = qv.w;
                float4 kv = Kb[row * 32 + kc * 8 + d4];
                Kt[(d4 * 4 + 0) * 132 + row] = kv.x;
                Kt[(d4 * 4 + 1) * 132 + row] = kv.y;
                Kt[(d4 * 4 + 2) * 132 + row] = kv.z;
                Kt[(d4 * 4 + 3) * 132 + row] = kv.w;
            }
            __syncthreads();
#pragma unroll 4
            for (int d = 0; d < 32; d++) {
                float a[8];
#pragma unroll
                for (int r = 0; r < 8; r++) a[r] = Qs[(ty * 8 + r) * 33 + d];
                float4 w0 = *(const float4*)&Kt[d * 132 + tx * 4];
                float4 w1 = *(const float4*)&Kt[d * 132 + 64 + tx * 4];
#pragma unroll
                for (int r = 0; r < 8; r++) {
                    acc[r][0] += a[r] * w0.x; acc[r][1] += a[r] * w0.y;
                    acc[r][2] += a[r] * w0.z; acc[r][3] += a[r] * w0.w;
                    acc[r][4] += a[r] * w1.x; acc[r][5] += a[r] * w1.y;
                    acc[r][6] += a[r] * w1.z; acc[r][7] += a[r] * w1.w;
                }
            }
            __syncthreads();
        }

#pragma unroll
        for (int r = 0; r < 8; r++) {
            float mi = sm_m[ty * 8 + r];
            float zi = sm_zi[ty * 8 + r];
#pragma unroll
            for (int c = 0; c < 8; c++)
                wacc[c] += __expf(acc[r][c] * SCALE - mi) * zi;
        }
        __syncthreads();  // protect sm_m/sm_zi before next iteration's overwrite
    }

#pragma unroll
    for (int c = 0; c < 4; c++) atomicAdd(&colw[tx * 4 + c], wacc[c]);
#pragma unroll
    for (int c = 4; c < 8; c++) atomicAdd(&colw[64 + tx * 4 + (c - 4)], wacc[c]);
    __syncthreads();
    if (tid < 128) g_w[g * NG + tj * 128 + tid] = colw[tid];
}

// ---------------- pooled = (1/n) sum_j w_j v_j; then MLP head ----------------
__global__ void __launch_bounds__(128) k_pooled_head(const float* __restrict__ Wh1,
                                                     const float* __restrict__ bh1,
                                                     const float* __restrict__ Wh2,
                                                     const float* __restrict__ bh2,
                                                     float* __restrict__ out) {
    int g = blockIdx.x, d = threadIdx.x;  // 128 threads
    __shared__ float ws[NG];
    __shared__ float pooled[HH];
    __shared__ float hid[64];
    for (int i = d; i < NG; i += 128) ws[i] = g_w[g * NG + i];
    __syncthreads();
    const float* vg = (const float*)g_hs + (size_t)g * NG * HH;  // V lives in g_hs
    float acc = 0.f;
    for (int j = 0; j < NG; j++) acc += ws[j] * vg[j * HH + d];
    pooled[d] = acc * (1.0f / (float)NG);
    __syncthreads();
    if (d < 64) {
        float h = bh1[d];
#pragma unroll 8
        for (int k = 0; k < HH; k++) h += pooled[k] * Wh1[k * 64 + d];
        hid[d] = fmaxf(h, 0.f);
    }
    __syncthreads();
    if (d == 0) {
        float o = bh2[0];
#pragma unroll 8
        for (int h = 0; h < 64; h++) o += hid[h] * Wh2[h];
        out[g] = o;
    }
}

// ---------------- launch: kernel launches ONLY ----------------
extern "C" void kernel_launch(void* const* d_in, const int* in_sizes, int n_in,
                              void* d_out, int out_size) {
    const float* x   = (const float*)d_in[0];
    const void*  ei  = d_in[1];
    // d_in[2] = batch (unused: equal sorted segments)
    const float* W1  = (const float*)d_in[3];
    const float* b1  = (const float*)d_in[4];
    const float* W2  = (const float*)d_in[5];
    const float* b2  = (const float*)d_in[6];
    const float* Wq  = (const float*)d_in[7];
    const float* bq  = (const float*)d_in[8];
    const float* Wk  = (const float*)d_in[9];
    const float* bk  = (const float*)d_in[10];
    const float* Wv  = (const float*)d_in[11];
    const float* bv  = (const float*)d_in[12];
    const float* Wh1 = (const float*)d_in[13];
    const float* bh1 = (const float*)d_in[14];
    const float* Wh2 = (const float*)d_in[15];
    const float* bh2 = (const float*)d_in[16];
    float* out = (float*)d_out;

    // dtype detect + CSR build + dinv
    k_dtype<<<1, 256>>>(ei);
    k_zero_cnt<<<NN / 256, 256>>>();
    k_hist<<<EE / 256, 256>>>(ei);
    k_scan<<<1, 1024>>>();
    k_fill<<<EE / 256, 256>>>(ei);

    // conv1: hs = (x@W1)*dinv ; h = relu(dinv * (self + gather) + b1)
    k_gemm<<<NN / 128, 256>>>(x, W1, nullptr, 0, 0, 1);
    k_aggregate<<<NN * 32 / 256, 256>>>(b1);

    // conv2
    k_gemm<<<NN / 128, 256>>>(nullptr, W2, nullptr, 1, 0, 1);
    k_aggregate<<<NN * 32 / 256, 256>>>(b2);

    // q, k (V last, into g_hs which is now dead)
    k_gemm<<<NN / 128, 256>>>(nullptr, Wq, bq, 1, 1, 0);
    k_gemm<<<NN / 128, 256>>>(nullptr, Wk, bk, 1, 2, 0);
    k_gemm<<<NN / 128, 256>>>(nullptr, Wv, bv, 1, 0, 0);

    // attention: row softmax stats, then column weights (scores recomputed)
    dim3 ra(NG / 128, GG);  // (4, 64)
    k_rowstats2<<<ra, 256>>>();
    k_colw<<<ra, 256>>>();
    k_pooled_head<<<GG, HH>>>(Wh1, bh1, Wh2, bh2, out);
}

// round 5
// speedup vs baseline: 1.3542x; 1.3542x over previous
#include <cuda_runtime.h>
#include <cstdint>
#include <cstddef>

#define NN 32768
#define EE 524288
#define HH 128
#define GG 64
#define NG 512   // nodes per graph

// ---------------- device scratch (static, no allocations; float4 => 16B aligned) ----------------
__device__ int    g_ei64;                      // 1 if edge_index is int64, 0 if int32
__device__ int    g_cnt[NN];                   // in-degree histogram (excl self-loop)
__device__ int    g_off[NN + 1];               // CSR offsets
__device__ int    g_cur[NN];                   // fill cursors
__device__ int    g_bsum[128];                 // scan block sums
__device__ int    g_boff[128];                 // scan block offsets
__device__ int    g_srcs[EE];                  // CSR source ids (grouped by dst)
__device__ float  g_dinv[NN];
__device__ float4 g_hs[NN * 32];               // messages; later reused for V
__device__ float4 g_h [NN * 32];               // post-conv features
__device__ float4 g_q [NN * 32];
__device__ float4 g_k [NN * 32];
__device__ float  g_scores[(size_t)GG * NG * NG]; // 64 MB scaled scores (L2-resident)
__device__ float  g_rowm[GG * NG];
__device__ float  g_rowz[GG * NG];             // 1/Z per row
__device__ float  g_w[GG * NG];                // column weights

// ---------------- f32x2 packed math helpers ----------------
__device__ __forceinline__ unsigned long long pk2(float lo, float hi) {
    unsigned long long r;
    asm("mov.b64 %0, {%1, %2};" : "=l"(r) : "f"(lo), "f"(hi));
    return r;
}
__device__ __forceinline__ void upk2(unsigned long long v, float& lo, float& hi) {
    asm("mov.b64 {%0, %1}, %2;" : "=f"(lo), "=f"(hi) : "l"(v));
}
__device__ __forceinline__ unsigned long long f2fma(unsigned long long a,
                                                    unsigned long long b,
                                                    unsigned long long c) {
    unsigned long long d;
    asm("fma.rn.f32x2 %0, %1, %2, %3;" : "=l"(d) : "l"(a), "l"(b), "l"(c));
    return d;
}

// ---------------- edge index accessors (dtype-flexible, trap-safe) ----------------
__device__ __forceinline__ int edge_src(const void* ei, int e) {
    int v = g_ei64 ? (int)((const long long*)ei)[e] : ((const int*)ei)[e];
    return v & (NN - 1);
}
__device__ __forceinline__ int edge_dst(const void* ei, int e) {
    int v = g_ei64 ? (int)((const long long*)ei)[EE + e] : ((const int*)ei)[EE + e];
    return v & (NN - 1);
}

// detect dtype: first 1024 int64-slots all in [0,NN) => int64 data (reads 8KB, safe either way)
__global__ void k_dtype(const void* ei) {
    __shared__ int s_ok;
    if (threadIdx.x == 0) s_ok = 1;
    __syncthreads();
    const long long* p = (const long long*)ei;
    int bad = 0;
#pragma unroll
    for (int i = 0; i < 4; i++) {
        long long v = p[threadIdx.x * 4 + i];
        if (v < 0 || v >= NN) bad = 1;
    }
    if (bad) atomicExch(&s_ok, 0);
    __syncthreads();
    if (threadIdx.x == 0) g_ei64 = s_ok;
}

// ---------------- CSR build ----------------
__global__ void k_zero_cnt() {
    int i = blockIdx.x * blockDim.x + threadIdx.x;
    if (i < NN) g_cnt[i] = 0;
}

__global__ void k_hist(const void* __restrict__ ei) {
    int e = blockIdx.x * blockDim.x + threadIdx.x;
    if (e < EE) atomicAdd(&g_cnt[edge_dst(ei, e)], 1);
}

// multi-block scan, stage 1: per-block exclusive scan + block sums
__global__ void __launch_bounds__(256) k_scan1() {
    __shared__ int sh[256];
    int t = threadIdx.x;
    int i = blockIdx.x * 256 + t;
    int c = g_cnt[i];
    sh[t] = c;
    __syncthreads();
#pragma unroll
    for (int o = 1; o < 256; o <<= 1) {
        int v = (t >= o) ? sh[t - o] : 0;
        __syncthreads();
        sh[t] += v;
        __syncthreads();
    }
    g_off[i] = sh[t] - c;                 // block-local exclusive prefix
    if (t == 255) g_bsum[blockIdx.x] = sh[255];
}

// stage 2: scan the 128 block sums
__global__ void __launch_bounds__(128) k_scan2() {
    __shared__ int sh[128];
    int t = threadIdx.x;
    int c = g_bsum[t];
    sh[t] = c;
    __syncthreads();
#pragma unroll
    for (int o = 1; o < 128; o <<= 1) {
        int v = (t >= o) ? sh[t - o] : 0;
        __syncthreads();
        sh[t] += v;
        __syncthreads();
    }
    g_boff[t] = sh[t] - c;
}

// stage 3: add block offsets, init cursors + dinv
__global__ void __launch_bounds__(256) k_scan3() {
    int i = blockIdx.x * 256 + threadIdx.x;
    int off = g_off[i] + g_boff[i >> 8];
    g_off[i] = off;
    g_cur[i] = off;
    g_dinv[i] = rsqrtf((float)g_cnt[i] + 1.0f);   // +1 self loop
    if (i == 0) g_off[NN] = EE;
}

__global__ void k_fill(const void* __restrict__ ei) {
    int e = blockIdx.x * blockDim.x + threadIdx.x;
    if (e >= EE) return;
    int s = edge_src(ei, e);
    int d = edge_dst(ei, e);
    int slot = atomicAdd(&g_cur[d], 1);
    g_srcs[slot] = s;
}

// ---------------- GEMM: C[M,128] = A[M,128] @ W[128,128]  (f32x2 packed FMA) ----------------
// 128x128 output tile per block, 256 threads, 8x8 microtile, K chunked by 32.
// srcMode: 0 = Aext (harness input), 1 = g_h
// dstMode: 0 = g_hs (also V), 1 = g_q, 2 = g_k
// useRow != 0: multiply rows by g_dinv (conv message scaling)
__global__ void __launch_bounds__(256) k_gemm(const float* __restrict__ Aext,
                                              const float* __restrict__ W,
                                              const float* __restrict__ bias,
                                              int srcMode, int dstMode, int useRow) {
    __shared__ __align__(16) float As[128 * 33];
    __shared__ __align__(16) float Ws[32 * 128];
    const float* A = (srcMode == 0) ? Aext : (const float*)g_h;
    float4* C = (dstMode == 0) ? g_hs : (dstMode == 1) ? g_q : g_k;

    int tid = threadIdx.x;
    size_t m0 = (size_t)blockIdx.x * 128;
    const float4* A4 = (const float4*)(A + m0 * 128);
    const float4* W4 = (const float4*)W;

    int ty = tid >> 4, tx = tid & 15;
    unsigned long long acc2[8][4];
#pragma unroll
    for (int r = 0; r < 8; r++)
#pragma unroll
        for (int c = 0; c < 4; c++) acc2[r][c] = 0ull;

    for (int kc = 0; kc < 4; kc++) {
#pragma unroll
        for (int it = 0; it < 4; it++) {
            int idx = it * 256 + tid;
            int row = idx >> 3, k4 = idx & 7;
            float4 v = A4[row * 32 + kc * 8 + k4];
            float* p = &As[row * 33 + k4 * 4];
            p[0] = v.x; p[1] = v.y; p[2] = v.z; p[3] = v.w;
        }
#pragma unroll
        for (int it = 0; it < 4; it++) {
            int idx = it * 256 + tid;
            int kr = idx >> 5, c4 = idx & 31;
            ((float4*)Ws)[kr * 32 + c4] = W4[(kc * 32 + kr) * 32 + c4];
        }
        __syncthreads();

#pragma unroll 4
        for (int k = 0; k < 32; k++) {
            double2 d0 = *(const double2*)&Ws[k * 128 + tx * 4];
            double2 d1 = *(const double2*)&Ws[k * 128 + 64 + tx * 4];
            unsigned long long w01 = __double_as_longlong(d0.x);
            unsigned long long w23 = __double_as_longlong(d0.y);
            unsigned long long w45 = __double_as_longlong(d1.x);
            unsigned long long w67 = __double_as_longlong(d1.y);
#pragma unroll
            for (int r = 0; r < 8; r++) {
                float a = As[(ty * 8 + r) * 33 + k];
                unsigned long long a2 = pk2(a, a);
                acc2[r][0] = f2fma(a2, w01, acc2[r][0]);
                acc2[r][1] = f2fma(a2, w23, acc2[r][1]);
                acc2[r][2] = f2fma(a2, w45, acc2[r][2]);
                acc2[r][3] = f2fma(a2, w67, acc2[r][3]);
            }
        }
        __syncthreads();
    }

    float4 b0 = make_float4(0.f, 0.f, 0.f, 0.f), b1v = b0;
    if (bias) { b0 = ((const float4*)bias)[tx]; b1v = ((const float4*)bias)[16 + tx]; }
#pragma unroll
    for (int r = 0; r < 8; r++) {
        size_t m = m0 + ty * 8 + r;
        float sc = useRow ? g_dinv[m] : 1.0f;
        float c[8];
        upk2(acc2[r][0], c[0], c[1]); upk2(acc2[r][1], c[2], c[3]);
        upk2(acc2[r][2], c[4], c[5]); upk2(acc2[r][3], c[6], c[7]);
        float4 o0, o1;
        o0.x = c[0] * sc + b0.x;  o0.y = c[1] * sc + b0.y;
        o0.z = c[2] * sc + b0.z;  o0.w = c[3] * sc + b0.w;
        o1.x = c[4] * sc + b1v.x; o1.y = c[5] * sc + b1v.y;
        o1.z = c[6] * sc + b1v.z; o1.w = c[7] * sc + b1v.w;
        C[m * 32 + tx] = o0;
        C[m * 32 + 16 + tx] = o1;
    }
}

// ---------------- aggregate: h[i] = relu(dinv[i] * (hs[i] + sum_{s->i} hs[s]) + b) ----------------
__global__ void __launch_bounds__(256) k_aggregate(const float* __restrict__ b) {
    int t = blockIdx.x * blockDim.x + threadIdx.x;
    int i = t >> 5;
    if (i >= NN) return;
    int lane = t & 31;

    float4 acc = g_hs[(size_t)i * 32 + lane];   // self loop (hs already has dinv[src])
    int j = g_off[i];
    int end = g_off[i + 1];
    for (; j + 1 < end; j += 2) {
        int s0 = g_srcs[j], s1 = g_srcs[j + 1];
        float4 v0 = g_hs[(size_t)s0 * 32 + lane];
        float4 v1 = g_hs[(size_t)s1 * 32 + lane];
        acc.x += v0.x + v1.x; acc.y += v0.y + v1.y;
        acc.z += v0.z + v1.z; acc.w += v0.w + v1.w;
    }
    if (j < end) {
        int s0 = g_srcs[j];
        float4 v0 = g_hs[(size_t)s0 * 32 + lane];
        acc.x += v0.x; acc.y += v0.y; acc.z += v0.z; acc.w += v0.w;
    }
    float sc = g_dinv[i];
    float4 bb = ((const float4*)b)[lane];
    float4 o;
    o.x = fmaxf(acc.x * sc + bb.x, 0.f);
    o.y = fmaxf(acc.y * sc + bb.y, 0.f);
    o.z = fmaxf(acc.z * sc + bb.z, 0.f);
    o.w = fmaxf(acc.w * sc + bb.w, 0.f);
    g_h[(size_t)i * 32 + lane] = o;
}

#define SCALE 0.08838834764831845f  // 1/sqrt(128)

// ---------------- scores: S[g] = Q_g @ K_g^T * SCALE, materialized (f32x2 FMA) ----------------
__global__ void __launch_bounds__(256) k_scores() {
    __shared__ __align__(16) float Qs[128 * 33];
    __shared__ __align__(16) float Kt[32 * 132];
    int tid = threadIdx.x;
    int g = blockIdx.z, ti = blockIdx.y, tj = blockIdx.x;

    const float4* Qb = g_q + ((size_t)(g * NG + ti * 128)) * 32;
    const float4* Kb = g_k + ((size_t)(g * NG + tj * 128)) * 32;

    int ty = tid >> 4, tx = tid & 15;
    unsigned long long acc2[8][4];
#pragma unroll
    for (int r = 0; r < 8; r++)
#pragma unroll
        for (int c = 0; c < 4; c++) acc2[r][c] = 0ull;

    for (int kc = 0; kc < 4; kc++) {
#pragma unroll
        for (int it = 0; it < 4; it++) {
            int idx = it * 256 + tid;
            int row = idx >> 3, d4 = idx & 7;
            float4 qv = Qb[row * 32 + kc * 8 + d4];
            float* p = &Qs[row * 33 + d4 * 4];
            p[0] = qv.x; p[1] = qv.y; p[2] = qv.z; p[3] = qv.w;
            float4 kv = Kb[row * 32 + kc * 8 + d4];
            Kt[(d4 * 4 + 0) * 132 + row] = kv.x;
            Kt[(d4 * 4 + 1) * 132 + row] = kv.y;
            Kt[(d4 * 4 + 2) * 132 + row] = kv.z;
            Kt[(d4 * 4 + 3) * 132 + row] = kv.w;
        }
        __syncthreads();
#pragma unroll 4
        for (int d = 0; d < 32; d++) {
            double2 d0 = *(const double2*)&Kt[d * 132 + tx * 4];
            double2 d1 = *(const double2*)&Kt[d * 132 + 64 + tx * 4];
            unsigned long long w01 = __double_as_longlong(d0.x);
            unsigned long long w23 = __double_as_longlong(d0.y);
            unsigned long long w45 = __double_as_longlong(d1.x);
            unsigned long long w67 = __double_as_longlong(d1.y);
#pragma unroll
            for (int r = 0; r < 8; r++) {
                float a = Qs[(ty * 8 + r) * 33 + d];
                unsigned long long a2 = pk2(a, a);
                acc2[r][0] = f2fma(a2, w01, acc2[r][0]);
                acc2[r][1] = f2fma(a2, w23, acc2[r][1]);
                acc2[r][2] = f2fma(a2, w45, acc2[r][2]);
                acc2[r][3] = f2fma(a2, w67, acc2[r][3]);
            }
        }
        __syncthreads();
    }

    float* Sg = g_scores + (size_t)g * NG * NG;
#pragma unroll
    for (int r = 0; r < 8; r++) {
        int i = ti * 128 + ty * 8 + r;
        float c[8];
        upk2(acc2[r][0], c[0], c[1]); upk2(acc2[r][1], c[2], c[3]);
        upk2(acc2[r][2], c[4], c[5]); upk2(acc2[r][3], c[6], c[7]);
        float4 o0, o1;
        o0.x = c[0] * SCALE; o0.y = c[1] * SCALE; o0.z = c[2] * SCALE; o0.w = c[3] * SCALE;
        o1.x = c[4] * SCALE; o1.y = c[5] * SCALE; o1.z = c[6] * SCALE; o1.w = c[7] * SCALE;
        *(float4*)(Sg + (size_t)i * NG + tj * 128 + tx * 4) = o0;
        *(float4*)(Sg + (size_t)i * NG + tj * 128 + 64 + tx * 4) = o1;
    }
}

// ---------------- per-row softmax stats: m_i, 1/Z_i; also zero g_w ----------------
__global__ void k_rowstats() {
    int gt = blockIdx.x * blockDim.x + threadIdx.x;
    int row = gt >> 5, lane = gt & 31;
    if (row >= GG * NG) return;
    const float* r = g_scores + (size_t)row * NG;
    float v[16];
    float m = -1e30f;
#pragma unroll
    for (int i = 0; i < 16; i++) { v[i] = r[lane + i * 32]; m = fmaxf(m, v[i]); }
#pragma unroll
    for (int o = 16; o > 0; o >>= 1) m = fmaxf(m, __shfl_xor_sync(0xffffffffu, m, o));
    float z = 0.f;
#pragma unroll
    for (int i = 0; i < 16; i++) z += __expf(v[i] - m);
#pragma unroll
    for (int o = 16; o > 0; o >>= 1) z += __shfl_xor_sync(0xffffffffu, z, o);
    if (lane == 0) { g_rowm[row] = m; g_rowz[row] = 1.0f / z; g_w[row] = 0.f; }
}

// ---------------- column weights: w_j += sum_{i in tile} exp(s_ij - m_i)/Z_i ----------------
// grid (GG, 4): each block covers 128 rows x all 512 columns of one graph
__global__ void __launch_bounds__(512) k_colsum() {
    __shared__ float sm_m[128];
    __shared__ float sm_zi[128];
    int g = blockIdx.x, it = blockIdx.y, j = threadIdx.x;
    if (j < 128) {
        sm_m[j]  = g_rowm[g * NG + it * 128 + j];
        sm_zi[j] = g_rowz[g * NG + it * 128 + j];
    }
    __syncthreads();
    const float* Sg = g_scores + (size_t)g * NG * NG + (size_t)it * 128 * NG;
    float w = 0.f;
#pragma unroll 4
    for (int i = 0; i < 128; i++)
        w += __expf(Sg[(size_t)i * NG + j] - sm_m[i]) * sm_zi[i];
    atomicAdd(&g_w[g * NG + j], w);
}

// ---------------- pooled = (1/n) sum_j w_j v_j; then MLP head ----------------
__global__ void __launch_bounds__(128) k_pooled_head(const float* __restrict__ Wh1,
                                                     const float* __restrict__ bh1,
                                                     const float* __restrict__ Wh2,
                                                     const float* __restrict__ bh2,
                                                     float* __restrict__ out) {
    int g = blockIdx.x, d = threadIdx.x;  // 128 threads
    __shared__ float ws[NG];
    __shared__ float pooled[HH];
    __shared__ float hid[64];
    for (int i = d; i < NG; i += 128) ws[i] = g_w[g * NG + i];
    __syncthreads();
    const float* vg = (const float*)g_hs + (size_t)g * NG * HH;  // V lives in g_hs
    float acc = 0.f;
    for (int j = 0; j < NG; j++) acc += ws[j] * vg[j * HH + d];
    pooled[d] = acc * (1.0f / (float)NG);
    __syncthreads();
    if (d < 64) {
        float h = bh1[d];
#pragma unroll 8
        for (int k = 0; k < HH; k++) h += pooled[k] * Wh1[k * 64 + d];
        hid[d] = fmaxf(h, 0.f);
    }
    __syncthreads();
    if (d == 0) {
        float o = bh2[0];
#pragma unroll 8
        for (int h = 0; h < 64; h++) o += hid[h] * Wh2[h];
        out[g] = o;
    }
}

// ---------------- launch: kernel launches ONLY ----------------
extern "C" void kernel_launch(void* const* d_in, const int* in_sizes, int n_in,
                              void* d_out, int out_size) {
    const float* x   = (const float*)d_in[0];
    const void*  ei  = d_in[1];
    // d_in[2] = batch (unused: equal sorted segments)
    const float* W1  = (const float*)d_in[3];
    const float* b1  = (const float*)d_in[4];
    const float* W2  = (const float*)d_in[5];
    const float* b2  = (const float*)d_in[6];
    const float* Wq  = (const float*)d_in[7];
    const float* bq  = (const float*)d_in[8];
    const float* Wk  = (const float*)d_in[9];
    const float* bk  = (const float*)d_in[10];
    const float* Wv  = (const float*)d_in[11];
    const float* bv  = (const float*)d_in[12];
    const float* Wh1 = (const float*)d_in[13];
    const float* bh1 = (const float*)d_in[14];
    const float* Wh2 = (const float*)d_in[15];
    const float* bh2 = (const float*)d_in[16];
    float* out = (float*)d_out;

    // dtype detect + CSR build + dinv
    k_dtype<<<1, 256>>>(ei);
    k_zero_cnt<<<NN / 256, 256>>>();
    k_hist<<<EE / 256, 256>>>(ei);
    k_scan1<<<NN / 256, 256>>>();
    k_scan2<<<1, 128>>>();
    k_scan3<<<NN / 256, 256>>>();
    k_fill<<<EE / 256, 256>>>(ei);

    // conv1: hs = (x@W1)*dinv ; h = relu(dinv * (self + gather) + b1)
    k_gemm<<<NN / 128, 256>>>(x, W1, nullptr, 0, 0, 1);
    k_aggregate<<<NN * 32 / 256, 256>>>(b1);

    // conv2
    k_gemm<<<NN / 128, 256>>>(nullptr, W2, nullptr, 1, 0, 1);
    k_aggregate<<<NN * 32 / 256, 256>>>(b2);

    // q, k (V last, into g_hs which is now dead)
    k_gemm<<<NN / 128, 256>>>(nullptr, Wq, bq, 1, 1, 0);
    k_gemm<<<NN / 128, 256>>>(nullptr, Wk, bk, 1, 2, 0);
    k_gemm<<<NN / 128, 256>>>(nullptr, Wv, bv, 1, 0, 0);

    // attention: materialize scaled scores once, then cheap softmax passes
    dim3 sg(NG / 128, NG / 128, GG);  // (4,4,64)
    k_scores<<<sg, 256>>>();
    k_rowstats<<<GG * NG * 32 / 256, 256>>>();
    dim3 cs(GG, NG / 128);            // (64,4)
    k_colsum<<<cs, 512>>>();
    k_pooled_head<<<GG, HH>>>(Wh1, bh1, Wh2, bh2, out);
}

// round 7
// speedup vs baseline: 1.4313x; 1.0569x over previous
#include <cuda_runtime.h>
#include <cuda_bf16.h>
#include <cstdint>
#include <cstddef>

#define NN 32768
#define EE 524288
#define HH 128
#define GG 64
#define NG 512   // nodes per graph

// ---------------- device scratch (static, no allocations) ----------------
__device__ int    g_ei64;
__device__ int    g_cnt[NN];
__device__ int    g_off[NN + 1];
__device__ int    g_cur[NN];
__device__ int    g_bsum[128];
__device__ int    g_boff[128];
__device__ int    g_srcs[EE];
__device__ float  g_dinv[NN];
__device__ float4 g_hs[NN * 32];               // messages; later reused for V
__device__ float4 g_h [NN * 32];
__device__ float4 g_q [NN * 32];
__device__ float4 g_k [NN * 32];
__device__ float  g_scores[(size_t)GG * NG * NG]; // 64 MB scaled scores
__device__ float  g_rowm[GG * NG];
__device__ float  g_rowz[GG * NG];
__device__ float  g_w[GG * NG];

// ---------------- bf16 mma.sync helpers (sm_80+ PTX, valid on compute_103) ----------------
#define MMA_BF16(D, a0, a1, a2, a3, b0, b1)                                   \
    asm volatile(                                                             \
        "mma.sync.aligned.m16n8k16.row.col.f32.bf16.bf16.f32 "                \
        "{%0,%1,%2,%3}, {%4,%5,%6,%7}, {%8,%9}, {%0,%1,%2,%3};"               \
        : "+f"((D)[0]), "+f"((D)[1]), "+f"((D)[2]), "+f"((D)[3])              \
        : "r"(a0), "r"(a1), "r"(a2), "r"(a3), "r"(b0), "r"(b1))

// padded row layout: 32 bf16 (one K-chunk) per row, padded to 80 bytes
#define PADB 80

// convert float4 -> hi/lo bf16x2 pairs, store 8B each at byte offset
__device__ __forceinline__ void cvt_pair(uint8_t* hi, uint8_t* lo,
                                         uint32_t off, float4 v) {
    __nv_bfloat16 hx = __float2bfloat16(v.x), hy = __float2bfloat16(v.y);
    __nv_bfloat16 hz = __float2bfloat16(v.z), hw = __float2bfloat16(v.w);
    __nv_bfloat162 h0 = __halves2bfloat162(hx, hy);
    __nv_bfloat162 h1 = __halves2bfloat162(hz, hw);
    *(uint2*)(hi + off) = make_uint2(*(uint32_t*)&h0, *(uint32_t*)&h1);
    __nv_bfloat162 l0 = __floats2bfloat162_rn(v.x - __bfloat162float(hx),
                                              v.y - __bfloat162float(hy));
    __nv_bfloat162 l1 = __floats2bfloat162_rn(v.z - __bfloat162float(hz),
                                              v.w - __bfloat162float(hw));
    *(uint2*)(lo + off) = make_uint2(*(uint32_t*)&l0, *(uint32_t*)&l1);
}

// ---------------- edge index accessors ----------------
__device__ __forceinline__ int edge_src(const void* ei, int e) {
    int v = g_ei64 ? (int)((const long long*)ei)[e] : ((const int*)ei)[e];
    return v & (NN - 1);
}
__device__ __forceinline__ int edge_dst(const void* ei, int e) {
    int v = g_ei64 ? (int)((const long long*)ei)[EE + e] : ((const int*)ei)[EE + e];
    return v & (NN - 1);
}

__global__ void k_dtype(const void* ei) {
    __shared__ int s_ok;
    if (threadIdx.x == 0) s_ok = 1;
    __syncthreads();
    const long long* p = (const long long*)ei;
    int bad = 0;
#pragma unroll
    for (int i = 0; i < 4; i++) {
        long long v = p[threadIdx.x * 4 + i];
        if (v < 0 || v >= NN) bad = 1;
    }
    if (bad) atomicExch(&s_ok, 0);
    __syncthreads();
    if (threadIdx.x == 0) g_ei64 = s_ok;
}

// ---------------- CSR build ----------------
__global__ void k_zero_cnt() {
    int i = blockIdx.x * blockDim.x + threadIdx.x;
    if (i < NN) g_cnt[i] = 0;
}
__global__ void k_hist(const void* __restrict__ ei) {
    int e = blockIdx.x * blockDim.x + threadIdx.x;
    if (e < EE) atomicAdd(&g_cnt[edge_dst(ei, e)], 1);
}
__global__ void __launch_bounds__(256) k_scan1() {
    __shared__ int sh[256];
    int t = threadIdx.x;
    int i = blockIdx.x * 256 + t;
    int c = g_cnt[i];
    sh[t] = c;
    __syncthreads();
#pragma unroll
    for (int o = 1; o < 256; o <<= 1) {
        int v = (t >= o) ? sh[t - o] : 0;
        __syncthreads();
        sh[t] += v;
        __syncthreads();
    }
    g_off[i] = sh[t] - c;
    if (t == 255) g_bsum[blockIdx.x] = sh[255];
}
__global__ void __launch_bounds__(128) k_scan2() {
    __shared__ int sh[128];
    int t = threadIdx.x;
    int c = g_bsum[t];
    sh[t] = c;
    __syncthreads();
#pragma unroll
    for (int o = 1; o < 128; o <<= 1) {
        int v = (t >= o) ? sh[t - o] : 0;
        __syncthreads();
        sh[t] += v;
        __syncthreads();
    }
    g_boff[t] = sh[t] - c;
}
__global__ void __launch_bounds__(256) k_scan3() {
    int i = blockIdx.x * 256 + threadIdx.x;
    int off = g_off[i] + g_boff[i >> 8];
    g_off[i] = off;
    g_cur[i] = off;
    g_dinv[i] = rsqrtf((float)g_cnt[i] + 1.0f);
    if (i == 0) g_off[NN] = EE;
}
__global__ void k_fill(const void* __restrict__ ei) {
    int e = blockIdx.x * blockDim.x + threadIdx.x;
    if (e >= EE) return;
    int s = edge_src(ei, e);
    int d = edge_dst(ei, e);
    int slot = atomicAdd(&g_cur[d], 1);
    g_srcs[slot] = s;
}

// ---------------- tensor GEMM (mma.sync bf16 split-3): C[128-tile,128] = A @ W ----------------
// 8 warps in 2x4; each warp 64x32; K chunked by 32; 40KB static smem.
__global__ void __launch_bounds__(256) k_tgemm(const float* __restrict__ Aext,
                                               const float* __restrict__ W,
                                               const float* __restrict__ bias,
                                               int srcMode, int dstMode, int useRow) {
    __shared__ __align__(16) uint8_t sA_hi[128 * PADB];
    __shared__ __align__(16) uint8_t sA_lo[128 * PADB];
    __shared__ __align__(16) uint8_t sB_hi[128 * PADB];
    __shared__ __align__(16) uint8_t sB_lo[128 * PADB];

    int tid = threadIdx.x, wid = tid >> 5, lane = tid & 31;
    int gid = lane >> 2, tig = lane & 3;
    int wm = wid >> 2, wn = wid & 3;

    const float* A = (srcMode == 0) ? Aext : (const float*)g_h;
    float* C = (float*)((dstMode == 0) ? g_hs : (dstMode == 1) ? g_q : g_k);
    size_t m0 = (size_t)blockIdx.x * 128;
    const float4* A4 = (const float4*)(A + m0 * 128);
    const float4* W4 = (const float4*)W;

    float d[4][4][4];
#pragma unroll
    for (int mt = 0; mt < 4; mt++)
#pragma unroll
        for (int nt = 0; nt < 4; nt++)
#pragma unroll
            for (int c = 0; c < 4; c++) d[mt][nt][c] = 0.f;

    for (int kc = 0; kc < 4; kc++) {
        // A chunk: 128 rows x 32 k (1024 float4)
#pragma unroll
        for (int it = 0; it < 4; it++) {
            int idx = it * 256 + tid;
            int row = idx >> 3, k4 = idx & 7;
            cvt_pair(sA_hi, sA_lo, row * PADB + k4 * 8, A4[row * 32 + kc * 8 + k4]);
        }
        // W chunk transposed into [n][k]: 32 k-rows x 128 cols
#pragma unroll
        for (int it = 0; it < 4; it++) {
            int idx = it * 256 + tid;
            int kr = idx >> 5, c4 = idx & 31;
            float4 v = W4[(kc * 32 + kr) * 32 + c4];
            float vv[4] = {v.x, v.y, v.z, v.w};
#pragma unroll
            for (int j = 0; j < 4; j++) {
                __nv_bfloat16 h = __float2bfloat16(vv[j]);
                __nv_bfloat16 l = __float2bfloat16(vv[j] - __bfloat162float(h));
                int n = c4 * 4 + j;
                *(__nv_bfloat16*)(sB_hi + n * PADB + kr * 2) = h;
                *(__nv_bfloat16*)(sB_lo + n * PADB + kr * 2) = l;
            }
        }
        __syncthreads();

#pragma unroll
        for (int ks = 0; ks < 2; ks++) {
            uint32_t bh[4][2], bl[4][2];
#pragma unroll
            for (int nt = 0; nt < 4; nt++) {
                int n = wn * 32 + nt * 8 + gid;
                const uint8_t* pb = sB_hi + n * PADB + ks * 32 + tig * 4;
                bh[nt][0] = *(const uint32_t*)pb;
                bh[nt][1] = *(const uint32_t*)(pb + 16);
                const uint8_t* pl = sB_lo + n * PADB + ks * 32 + tig * 4;
                bl[nt][0] = *(const uint32_t*)pl;
                bl[nt][1] = *(const uint32_t*)(pl + 16);
            }
#pragma unroll
            for (int mt = 0; mt < 4; mt++) {
                int r = wm * 64 + mt * 16 + gid;
                const uint8_t* pa  = sA_hi + r * PADB + ks * 32 + tig * 4;
                const uint8_t* pa8 = pa + 8 * PADB;
                uint32_t ah0 = *(const uint32_t*)pa,        ah1 = *(const uint32_t*)pa8;
                uint32_t ah2 = *(const uint32_t*)(pa + 16), ah3 = *(const uint32_t*)(pa8 + 16);
                const uint8_t* qa  = sA_lo + r * PADB + ks * 32 + tig * 4;
                const uint8_t* qa8 = qa + 8 * PADB;
                uint32_t al0 = *(const uint32_t*)qa,        al1 = *(const uint32_t*)qa8;
                uint32_t al2 = *(const uint32_t*)(qa + 16), al3 = *(const uint32_t*)(qa8 + 16);
#pragma unroll
                for (int nt = 0; nt < 4; nt++) {
                    MMA_BF16(d[mt][nt], ah0, ah1, ah2, ah3, bh[nt][0], bh[nt][1]);
                    MMA_BF16(d[mt][nt], ah0, ah1, ah2, ah3, bl[nt][0], bl[nt][1]);
                    MMA_BF16(d[mt][nt], al0, al1, al2, al3, bh[nt][0], bh[nt][1]);
                }
            }
        }
        __syncthreads();
    }

    // epilogue: d0,d1 -> (row, col..col+1); d2,d3 -> (row+8, ...)
#pragma unroll
    for (int mt = 0; mt < 4; mt++) {
        size_t row0 = m0 + wm * 64 + mt * 16 + gid;
        size_t row1 = row0 + 8;
        float sc0 = useRow ? g_dinv[row0] : 1.0f;
        float sc1 = useRow ? g_dinv[row1] : 1.0f;
#pragma unroll
        for (int nt = 0; nt < 4; nt++) {
            int col = wn * 32 + nt * 8 + tig * 2;
            float bx = 0.f, by = 0.f;
            if (bias) { bx = bias[col]; by = bias[col + 1]; }
            float2 o0 = make_float2(d[mt][nt][0] * sc0 + bx, d[mt][nt][1] * sc0 + by);
            float2 o1 = make_float2(d[mt][nt][2] * sc1 + bx, d[mt][nt][3] * sc1 + by);
            *(float2*)(C + row0 * 128 + col) = o0;
            *(float2*)(C + row1 * 128 + col) = o1;
        }
    }
}

// ---------------- scores via mma.sync: S-tile = Q @ K^T * SCALE ----------------
#define SCALE 0.08838834764831845f

__global__ void __launch_bounds__(256) k_tscores() {
    __shared__ __align__(16) uint8_t sA_hi[128 * PADB];
    __shared__ __align__(16) uint8_t sA_lo[128 * PADB];
    __shared__ __align__(16) uint8_t sB_hi[128 * PADB];
    __shared__ __align__(16) uint8_t sB_lo[128 * PADB];

    int tid = threadIdx.x, wid = tid >> 5, lane = tid & 31;
    int gid = lane >> 2, tig = lane & 3;
    int wm = wid >> 2, wn = wid & 3;
    int g = blockIdx.z, ti = blockIdx.y, tj = blockIdx.x;

    const float4* Q4 = g_q + ((size_t)(g * NG + ti * 128)) * 32;
    const float4* K4 = g_k + ((size_t)(g * NG + tj * 128)) * 32;

    float d[4][4][4];
#pragma unroll
    for (int mt = 0; mt < 4; mt++)
#pragma unroll
        for (int nt = 0; nt < 4; nt++)
#pragma unroll
            for (int c = 0; c < 4; c++) d[mt][nt][c] = 0.f;

    for (int kc = 0; kc < 4; kc++) {
#pragma unroll
        for (int it = 0; it < 4; it++) {
            int idx = it * 256 + tid;
            int row = idx >> 3, k4 = idx & 7;
            uint32_t off = row * PADB + k4 * 8;
            cvt_pair(sA_hi, sA_lo, off, Q4[row * 32 + kc * 8 + k4]);
            cvt_pair(sB_hi, sB_lo, off, K4[row * 32 + kc * 8 + k4]);
        }
        __syncthreads();

#pragma unroll
        for (int ks = 0; ks < 2; ks++) {
            uint32_t bh[4][2], bl[4][2];
#pragma unroll
            for (int nt = 0; nt < 4; nt++) {
                int n = wn * 32 + nt * 8 + gid;
                const uint8_t* pb = sB_hi + n * PADB + ks * 32 + tig * 4;
                bh[nt][0] = *(const uint32_t*)pb;
                bh[nt][1] = *(const uint32_t*)(pb + 16);
                const uint8_t* pl = sB_lo + n * PADB + ks * 32 + tig * 4;
                bl[nt][0] = *(const uint32_t*)pl;
                bl[nt][1] = *(const uint32_t*)(pl + 16);
            }
#pragma unroll
            for (int mt = 0; mt < 4; mt++) {
                int r = wm * 64 + mt * 16 + gid;
                const uint8_t* pa  = sA_hi + r * PADB + ks * 32 + tig * 4;
                const uint8_t* pa8 = pa + 8 * PADB;
                uint32_t ah0 = *(const uint32_t*)pa,        ah1 = *(const uint32_t*)pa8;
                uint32_t ah2 = *(const uint32_t*)(pa + 16), ah3 = *(const uint32_t*)(pa8 + 16);
                const uint8_t* qa  = sA_lo + r * PADB + ks * 32 + tig * 4;
                const uint8_t* qa8 = qa + 8 * PADB;
                uint32_t al0 = *(const uint32_t*)qa,        al1 = *(const uint32_t*)qa8;
                uint32_t al2 = *(const uint32_t*)(qa + 16), al3 = *(const uint32_t*)(qa8 + 16);
#pragma unroll
                for (int nt = 0; nt < 4; nt++) {
                    MMA_BF16(d[mt][nt], ah0, ah1, ah2, ah3, bh[nt][0], bh[nt][1]);
                    MMA_BF16(d[mt][nt], ah0, ah1, ah2, ah3, bl[nt][0], bl[nt][1]);
                    MMA_BF16(d[mt][nt], al0, al1, al2, al3, bh[nt][0], bh[nt][1]);
                }
            }
        }
        __syncthreads();
    }

    float* Sg = g_scores + (size_t)g * NG * NG;
#pragma unroll
    for (int mt = 0; mt < 4; mt++) {
        int i0 = ti * 128 + wm * 64 + mt * 16 + gid;
        int i1 = i0 + 8;
#pragma unroll
        for (int nt = 0; nt < 4; nt++) {
            int col = tj * 128 + wn * 32 + nt * 8 + tig * 2;
            float2 o0 = make_float2(d[mt][nt][0] * SCALE, d[mt][nt][1] * SCALE);
            float2 o1 = make_float2(d[mt][nt][2] * SCALE, d[mt][nt][3] * SCALE);
            *(float2*)(Sg + (size_t)i0 * NG + col) = o0;
            *(float2*)(Sg + (size_t)i1 * NG + col) = o1;
        }
    }
}

// ---------------- aggregate: h[i] = relu(dinv[i] * (hs[i] + sum_{s->i} hs[s]) + b) ----------------
__global__ void __launch_bounds__(256) k_aggregate(const float* __restrict__ b) {
    int t = blockIdx.x * blockDim.x + threadIdx.x;
    int i = t >> 5;
    if (i >= NN) return;
    int lane = t & 31;

    float4 acc = g_hs[(size_t)i * 32 + lane];
    int j = g_off[i];
    int end = g_off[i + 1];
    for (; j + 1 < end; j += 2) {
        int s0 = g_srcs[j], s1 = g_srcs[j + 1];
        float4 v0 = g_hs[(size_t)s0 * 32 + lane];
        float4 v1 = g_hs[(size_t)s1 * 32 + lane];
        acc.x += v0.x + v1.x; acc.y += v0.y + v1.y;
        acc.z += v0.z + v1.z; acc.w += v0.w + v1.w;
    }
    if (j < end) {
        int s0 = g_srcs[j];
        float4 v0 = g_hs[(size_t)s0 * 32 + lane];
        acc.x += v0.x; acc.y += v0.y; acc.z += v0.z; acc.w += v0.w;
    }
    float sc = g_dinv[i];
    float4 bb = ((const float4*)b)[lane];
    float4 o;
    o.x = fmaxf(acc.x * sc + bb.x, 0.f);
    o.y = fmaxf(acc.y * sc + bb.y, 0.f);
    o.z = fmaxf(acc.z * sc + bb.z, 0.f);
    o.w = fmaxf(acc.w * sc + bb.w, 0.f);
    g_h[(size_t)i * 32 + lane] = o;
}

// ---------------- per-row softmax stats ----------------
__global__ void k_rowstats() {
    int gt = blockIdx.x * blockDim.x + threadIdx.x;
    int row = gt >> 5, lane = gt & 31;
    if (row >= GG * NG) return;
    const float* r = g_scores + (size_t)row * NG;
    float v[16];
    float m = -1e30f;
#pragma unroll
    for (int i = 0; i < 16; i++) { v[i] = r[lane + i * 32]; m = fmaxf(m, v[i]); }
#pragma unroll
    for (int o = 16; o > 0; o >>= 1) m = fmaxf(m, __shfl_xor_sync(0xffffffffu, m, o));
    float z = 0.f;
#pragma unroll
    for (int i = 0; i < 16; i++) z += __expf(v[i] - m);
#pragma unroll
    for (int o = 16; o > 0; o >>= 1) z += __shfl_xor_sync(0xffffffffu, z, o);
    if (lane == 0) { g_rowm[row] = m; g_rowz[row] = 1.0f / z; g_w[row] = 0.f; }
}

// ---------------- column weights ----------------
__global__ void __launch_bounds__(512) k_colsum() {
    __shared__ float sm_m[128];
    __shared__ float sm_zi[128];
    int g = blockIdx.x, it = blockIdx.y, j = threadIdx.x;
    if (j < 128) {
        sm_m[j]  = g_rowm[g * NG + it * 128 + j];
        sm_zi[j] = g_rowz[g * NG + it * 128 + j];
    }
    __syncthreads();
    const float* Sg = g_scores + (size_t)g * NG * NG + (size_t)it * 128 * NG;
    float w = 0.f;
#pragma unroll 4
    for (int i = 0; i < 128; i++)
        w += __expf(Sg[(size_t)i * NG + j] - sm_m[i]) * sm_zi[i];
    atomicAdd(&g_w[g * NG + j], w);
}

// ---------------- pooled + MLP head ----------------
__global__ void __launch_bounds__(128) k_pooled_head(const float* __restrict__ Wh1,
                                                     const float* __restrict__ bh1,
                                                     const float* __restrict__ Wh2,
                                                     const float* __restrict__ bh2,
                                                     float* __restrict__ out) {
    int g = blockIdx.x, d = threadIdx.x;
    __shared__ float ws[NG];
    __shared__ float pooled[HH];
    __shared__ float hid[64];
    for (int i = d; i < NG; i += 128) ws[i] = g_w[g * NG + i];
    __syncthreads();
    const float* vg = (const float*)g_hs + (size_t)g * NG * HH;
    float acc = 0.f;
    for (int j = 0; j < NG; j++) acc += ws[j] * vg[j * HH + d];
    pooled[d] = acc * (1.0f / (float)NG);
    __syncthreads();
    if (d < 64) {
        float h = bh1[d];
#pragma unroll 8
        for (int k = 0; k < HH; k++) h += pooled[k] * Wh1[k * 64 + d];
        hid[d] = fmaxf(h, 0.f);
    }
    __syncthreads();
    if (d == 0) {
        float o = bh2[0];
#pragma unroll 8
        for (int h = 0; h < 64; h++) o += hid[h] * Wh2[h];
        out[g] = o;
    }
}

// ---------------- launch ----------------
extern "C" void kernel_launch(void* const* d_in, const int* in_sizes, int n_in,
                              void* d_out, int out_size) {
    const float* x   = (const float*)d_in[0];
    const void*  ei  = d_in[1];
    const float* W1  = (const float*)d_in[3];
    const float* b1  = (const float*)d_in[4];
    const float* W2  = (const float*)d_in[5];
    const float* b2  = (const float*)d_in[6];
    const float* Wq  = (const float*)d_in[7];
    const float* bq  = (const float*)d_in[8];
    const float* Wk  = (const float*)d_in[9];
    const float* bk  = (const float*)d_in[10];
    const float* Wv  = (const float*)d_in[11];
    const float* bv  = (const float*)d_in[12];
    const float* Wh1 = (const float*)d_in[13];
    const float* bh1 = (const float*)d_in[14];
    const float* Wh2 = (const float*)d_in[15];
    const float* bh2 = (const float*)d_in[16];
    float* out = (float*)d_out;

    // dtype detect + CSR build + dinv
    k_dtype<<<1, 256>>>(ei);
    k_zero_cnt<<<NN / 256, 256>>>();
    k_hist<<<EE / 256, 256>>>(ei);
    k_scan1<<<NN / 256, 256>>>();
    k_scan2<<<1, 128>>>();
    k_scan3<<<NN / 256, 256>>>();
    k_fill<<<EE / 256, 256>>>(ei);

    // conv1
    k_tgemm<<<NN / 128, 256>>>(x, W1, nullptr, 0, 0, 1);
    k_aggregate<<<NN * 32 / 256, 256>>>(b1);
    // conv2
    k_tgemm<<<NN / 128, 256>>>(nullptr, W2, nullptr, 1, 0, 1);
    k_aggregate<<<NN * 32 / 256, 256>>>(b2);
    // q, k, v (v into g_hs)
    k_tgemm<<<NN / 128, 256>>>(nullptr, Wq, bq, 1, 1, 0);
    k_tgemm<<<NN / 128, 256>>>(nullptr, Wk, bk, 1, 2, 0);
    k_tgemm<<<NN / 128, 256>>>(nullptr, Wv, bv, 1, 0, 0);

    // attention
    dim3 sg(NG / 128, NG / 128, GG);
    k_tscores<<<sg, 256>>>();
    k_rowstats<<<GG * NG * 32 / 256, 256>>>();
    dim3 cs(GG, NG / 128);
    k_colsum<<<cs, 512>>>();
    k_pooled_head<<<GG, HH>>>(Wh1, bh1, Wh2, bh2, out);
}